// round 2
// baseline (speedup 1.0000x reference)
#include <cuda_runtime.h>

// Problem constants (fixed by the dataset)
#define N_NODES  100000
#define N_EDGES  1600000
#define N_GRAPHS 512
#define F        32

// ---------------- scratch (static __device__ globals; no allocation) -------
__device__ __align__(128) float g_dinv[N_NODES];        // deg -> dinv (in place)
__device__ __align__(128) float g_bufA[N_NODES * F];    // xw1 then xw2
__device__ __align__(128) float g_bufB[N_NODES * F];    // agg1 then agg2
__device__ __align__(128) float g_norm[N_EDGES];
__device__ __align__(128) float g_sums[N_GRAPHS * F];
__device__ __align__(128) float g_cnt[N_GRAPHS];

// ---------------- K0: init deg=1 (self loop), zero pool accumulators -------
__global__ void k_init() {
    int i = blockIdx.x * blockDim.x + threadIdx.x;
    if (i < N_NODES) g_dinv[i] = 1.0f;
    if (i < N_GRAPHS * F) g_sums[i] = 0.0f;
    if (i < N_GRAPHS) g_cnt[i] = 0.0f;
}

// ---------------- K1: degree atomics (edge_index is int32) -----------------
__global__ void k_deg(const int* __restrict__ ei) {
    int e = blockIdx.x * blockDim.x + threadIdx.x;
    if (e >= N_EDGES) return;
    int d = ei[N_EDGES + e];
    atomicAdd(&g_dinv[d], 1.0f);
}

// ---------------- K2: dinv = rsqrt(deg); xw1 = x@W1; agg1 = xw1*dinv^2 -----
__global__ void k_l1_init(const float* __restrict__ x,
                          const float* __restrict__ W1) {
    int idx = blockIdx.x * blockDim.x + threadIdx.x;
    if (idx >= N_NODES * F) return;
    int n = idx >> 5, f = idx & 31;
    float deg = g_dinv[n];
    float di  = rsqrtf(deg);
    if (f == 0) g_dinv[n] = di;  // every lane computed di from its own read
    float x0 = x[n * 3 + 0], x1 = x[n * 3 + 1], x2 = x[n * 3 + 2];
    float a = x0 * W1[f] + x1 * W1[F + f] + x2 * W1[2 * F + f];
    g_bufA[idx] = a;
    g_bufB[idx] = a * di * di;   // self-loop term seeds the accumulator
}

// ---------------- K3/K5: edge aggregation (8 lanes/edge, v4 RED) -----------
// LOAD_NORM=false -> layer1: compute norm from dinv and cache it
// LOAD_NORM=true  -> layer2: read cached norm
template <bool LOAD_NORM>
__global__ void k_edge_agg(const int* __restrict__ ei) {
    long long t = (long long)blockIdx.x * blockDim.x + threadIdx.x;
    if (t >= (long long)N_EDGES * 8) return;
    int e = (int)(t >> 3), q = (int)(t & 7);
    int s = ei[e];
    int d = ei[N_EDGES + e];
    float nm;
    if (LOAD_NORM) {
        nm = g_norm[e];
    } else {
        nm = g_dinv[s] * g_dinv[d];
        if (q == 0) g_norm[e] = nm;
    }
    const float4 v = *reinterpret_cast<const float4*>(&g_bufA[s * F + q * 4]);
    float* p = &g_bufB[d * F + q * 4];
    asm volatile("red.global.add.v4.f32 [%0], {%1,%2,%3,%4};"
                 :: "l"(p), "f"(v.x * nm), "f"(v.y * nm),
                    "f"(v.z * nm), "f"(v.w * nm)
                 : "memory");
}

// ---------------- K4: h1=relu(agg1+b1); xw2=h1@W2; agg2=xw2*dinv^2 ---------
__global__ void k_relu_mm(const float* __restrict__ b1,
                          const float* __restrict__ W2) {
    __shared__ float W2s[F * F];
    int tid = threadIdx.x;
    for (int i = tid; i < F * F; i += blockDim.x) W2s[i] = W2[i];
    __syncthreads();
    int warp = (blockIdx.x * blockDim.x + tid) >> 5;
    int lane = tid & 31;
    if (warp >= N_NODES) return;
    float h = fmaxf(g_bufB[warp * F + lane] + b1[lane], 0.0f);
    float acc = 0.0f;
#pragma unroll
    for (int k = 0; k < F; k++) {
        float hk = __shfl_sync(0xffffffffu, h, k);
        acc = fmaf(hk, W2s[k * F + lane], acc);
    }
    float di = g_dinv[warp];
    g_bufA[warp * F + lane] = acc;
    g_bufB[warp * F + lane] = acc * di * di;
}

// ---------------- K6: h2=relu(agg2+b2); pool-sum by graph ------------------
__global__ void k_pool(const float* __restrict__ b2,
                       const int* __restrict__ batch) {
    int warp = (blockIdx.x * blockDim.x + threadIdx.x) >> 5;
    int lane = threadIdx.x & 31;
    if (warp >= N_NODES) return;
    float h = fmaxf(g_bufB[warp * F + lane] + b2[lane], 0.0f);
    int g = batch[warp];
    atomicAdd(&g_sums[g * F + lane], h);
    if (lane == 0) atomicAdd(&g_cnt[g], 1.0f);
}

// ---------------- K7: out = (sums/cnt)@Wl + bl -----------------------------
__global__ void k_out(const float* __restrict__ Wl,
                      const float* __restrict__ bl,
                      float* __restrict__ out) {
    int idx = blockIdx.x * blockDim.x + threadIdx.x;
    if (idx >= N_GRAPHS * 2) return;
    int g = idx >> 1, j = idx & 1;
    float inv = 1.0f / fmaxf(g_cnt[g], 1.0f);
    float acc = 0.0f;
#pragma unroll
    for (int f = 0; f < F; f++) acc += g_sums[g * F + f] * Wl[f * 2 + j];
    out[idx] = acc * inv + bl[j];
}

// ---------------- launch ---------------------------------------------------
extern "C" void kernel_launch(void* const* d_in, const int* in_sizes, int n_in,
                              void* d_out, int out_size) {
    const float* x     = (const float*)d_in[0];
    const int*   ei    = (const int*)d_in[1];      // int64 downcast to int32 by harness
    const int*   batch = (const int*)d_in[2];
    const float* W1    = (const float*)d_in[3];
    const float* b1    = (const float*)d_in[4];
    const float* W2    = (const float*)d_in[5];
    const float* b2    = (const float*)d_in[6];
    const float* Wl    = (const float*)d_in[7];
    const float* bl    = (const float*)d_in[8];
    float*       out   = (float*)d_out;

    const int TB = 256;
    k_init<<<(N_NODES + TB - 1) / TB, TB>>>();
    k_deg<<<(N_EDGES + TB - 1) / TB, TB>>>(ei);
    k_l1_init<<<(N_NODES * F + TB - 1) / TB, TB>>>(x, W1);
    k_edge_agg<false><<<(N_EDGES * 8 + TB - 1) / TB, TB>>>(ei);
    k_relu_mm<<<(N_NODES * F + TB - 1) / TB, TB>>>(b1, W2);
    k_edge_agg<true><<<(N_EDGES * 8 + TB - 1) / TB, TB>>>(ei);
    k_pool<<<(N_NODES * F + TB - 1) / TB, TB>>>(b2, batch);
    k_out<<<(N_GRAPHS * 2 + TB - 1) / TB, TB>>>(Wl, bl, out);
}

// round 3
// speedup vs baseline: 1.0625x; 1.0625x over previous
#include <cuda_runtime.h>

#define N_NODES  100000
#define N_EDGES  1600000
#define N_GRAPHS 512
#define F        32

#define SCAN_B   1024
#define NB       ((N_NODES + SCAN_B - 1) / SCAN_B)   // 98 scan blocks

// ---------------- scratch (static __device__ globals) ----------------------
__device__ __align__(128) int   g_hist[N_NODES];        // in-degree (no self loop)
__device__ __align__(128) int   g_off[N_NODES + 1];     // CSR offsets
__device__ __align__(128) int   g_pos[N_NODES];         // scatter cursors
__device__ __align__(128) int   g_blocksum[NB];
__device__ __align__(128) int   g_blockoff[NB];
__device__ __align__(128) int2  g_csr[N_EDGES];         // (src, norm-as-bits)
__device__ __align__(128) float g_dinv[N_NODES];
__device__ __align__(128) float g_bufA[N_NODES * F];    // xw1
__device__ __align__(128) float g_bufB[N_NODES * F];    // xw2 (after agg1 fusion)
__device__ __align__(128) float g_sums[N_GRAPHS * F];
__device__ __align__(128) float g_cnt[N_GRAPHS];

// ---------------- K0: zero hist + pool accumulators ------------------------
__global__ void k_init() {
    int i = blockIdx.x * blockDim.x + threadIdx.x;
    if (i < N_NODES) g_hist[i] = 0;
    if (i < N_GRAPHS * F) g_sums[i] = 0.0f;
    if (i < N_GRAPHS) g_cnt[i] = 0.0f;
}

// ---------------- K1: in-degree histogram ----------------------------------
__global__ void k_hist(const int* __restrict__ ei) {
    int e = blockIdx.x * blockDim.x + threadIdx.x;
    if (e >= N_EDGES) return;
    atomicAdd(&g_hist[ei[N_EDGES + e]], 1);
}

// ---------------- K2a/b/c: exclusive scan of hist -> off -------------------
__global__ void k_scan1() {
    __shared__ int sh[SCAN_B];
    int tid = threadIdx.x;
    int i = blockIdx.x * SCAN_B + tid;
    int v = (i < N_NODES) ? g_hist[i] : 0;
    sh[tid] = v;
    __syncthreads();
#pragma unroll
    for (int off = 1; off < SCAN_B; off <<= 1) {
        int t = (tid >= off) ? sh[tid - off] : 0;
        __syncthreads();
        sh[tid] += t;
        __syncthreads();
    }
    if (i < N_NODES) g_off[i] = sh[tid] - v;       // exclusive (local)
    if (tid == SCAN_B - 1) g_blocksum[blockIdx.x] = sh[tid];
}

__global__ void k_scan2() {
    __shared__ int sh[128];
    int tid = threadIdx.x;
    int v = (tid < NB) ? g_blocksum[tid] : 0;
    sh[tid] = v;
    __syncthreads();
#pragma unroll
    for (int off = 1; off < 128; off <<= 1) {
        int t = (tid >= off) ? sh[tid - off] : 0;
        __syncthreads();
        sh[tid] += t;
        __syncthreads();
    }
    if (tid < NB) g_blockoff[tid] = sh[tid] - v;   // exclusive
}

__global__ void k_scan3() {
    int i = blockIdx.x * blockDim.x + threadIdx.x;
    if (i < N_NODES) {
        int o = g_off[i] + g_blockoff[i / SCAN_B];
        g_off[i] = o;
        g_pos[i] = o;
    }
    if (i == 0) g_off[N_NODES] = N_EDGES;
}

// ---------------- K3: dinv = rsqrt(deg+1); xw1 = x@W1 ----------------------
__global__ void k_l1_init(const float* __restrict__ x,
                          const float* __restrict__ W1) {
    int idx = blockIdx.x * blockDim.x + threadIdx.x;
    if (idx >= N_NODES * F) return;
    int n = idx >> 5, f = idx & 31;
    float di = rsqrtf((float)g_hist[n] + 1.0f);
    if (f == 0) g_dinv[n] = di;
    float x0 = x[n * 3 + 0], x1 = x[n * 3 + 1], x2 = x[n * 3 + 2];
    g_bufA[idx] = x0 * W1[f] + x1 * W1[F + f] + x2 * W1[2 * F + f];
}

// ---------------- K4: scatter (src, norm) into CSR -------------------------
__global__ void k_scatter(const int* __restrict__ ei) {
    int e = blockIdx.x * blockDim.x + threadIdx.x;
    if (e >= N_EDGES) return;
    int s = ei[e];
    int d = ei[N_EDGES + e];
    int p = atomicAdd(&g_pos[d], 1);
    float nm = g_dinv[s] * g_dinv[d];
    g_csr[p] = make_int2(s, __float_as_int(nm));
}

// ---------------- K5: agg layer1 + relu(b1) + @W2 fused --------------------
// one warp per dst node; lane = feature column
__global__ void k_agg1(const float* __restrict__ b1,
                       const float* __restrict__ W2) {
    __shared__ float W2s[F * F];
    int tid = threadIdx.x;
    for (int i = tid; i < F * F; i += blockDim.x) W2s[i] = W2[i];
    __syncthreads();
    int w = (blockIdx.x * blockDim.x + tid) >> 5;
    int lane = tid & 31;
    if (w >= N_NODES) return;
    int beg = g_off[w], end = g_off[w + 1];
    float di = g_dinv[w];
    float acc = g_bufA[w * F + lane] * di * di;        // self loop
    for (int base = beg; base < end; base += 32) {
        int idx = base + lane;
        int2 rec = (idx < end) ? g_csr[idx] : make_int2(0, 0);
        int cnt = min(32, end - base);
        for (int j = 0; j < cnt; j++) {
            int   s  = __shfl_sync(0xffffffffu, rec.x, j);
            float nm = __int_as_float(__shfl_sync(0xffffffffu, rec.y, j));
            acc = fmaf(g_bufA[s * F + lane], nm, acc);
        }
    }
    // epilogue: h1 = relu(acc + b1); xw2 = h1 @ W2
    float h = fmaxf(acc + b1[lane], 0.0f);
    float o = 0.0f;
#pragma unroll
    for (int k = 0; k < F; k++) {
        float hk = __shfl_sync(0xffffffffu, h, k);
        o = fmaf(hk, W2s[k * F + lane], o);
    }
    g_bufB[w * F + lane] = o;
}

// ---------------- K6: agg layer2 + relu(b2) + pool fused -------------------
__global__ void k_agg2(const float* __restrict__ b2,
                       const int* __restrict__ batch) {
    int tid = threadIdx.x;
    int w = (blockIdx.x * blockDim.x + tid) >> 5;
    int lane = tid & 31;
    if (w >= N_NODES) return;
    int beg = g_off[w], end = g_off[w + 1];
    float di = g_dinv[w];
    float acc = g_bufB[w * F + lane] * di * di;        // self loop
    for (int base = beg; base < end; base += 32) {
        int idx = base + lane;
        int2 rec = (idx < end) ? g_csr[idx] : make_int2(0, 0);
        int cnt = min(32, end - base);
        for (int j = 0; j < cnt; j++) {
            int   s  = __shfl_sync(0xffffffffu, rec.x, j);
            float nm = __int_as_float(__shfl_sync(0xffffffffu, rec.y, j));
            acc = fmaf(g_bufB[s * F + lane], nm, acc);
        }
    }
    float h = fmaxf(acc + b2[lane], 0.0f);
    int g = batch[w];
    atomicAdd(&g_sums[g * F + lane], h);
    if (lane == 0) atomicAdd(&g_cnt[g], 1.0f);
}

// ---------------- K7: out = (sums/cnt)@Wl + bl -----------------------------
__global__ void k_out(const float* __restrict__ Wl,
                      const float* __restrict__ bl,
                      float* __restrict__ out) {
    int idx = blockIdx.x * blockDim.x + threadIdx.x;
    if (idx >= N_GRAPHS * 2) return;
    int g = idx >> 1, j = idx & 1;
    float inv = 1.0f / fmaxf(g_cnt[g], 1.0f);
    float acc = 0.0f;
#pragma unroll
    for (int f = 0; f < F; f++) acc += g_sums[g * F + f] * Wl[f * 2 + j];
    out[idx] = acc * inv + bl[j];
}

// ---------------- launch ---------------------------------------------------
extern "C" void kernel_launch(void* const* d_in, const int* in_sizes, int n_in,
                              void* d_out, int out_size) {
    const float* x     = (const float*)d_in[0];
    const int*   ei    = (const int*)d_in[1];    // int64 -> int32 by harness
    const int*   batch = (const int*)d_in[2];
    const float* W1    = (const float*)d_in[3];
    const float* b1    = (const float*)d_in[4];
    const float* W2    = (const float*)d_in[5];
    const float* b2    = (const float*)d_in[6];
    const float* Wl    = (const float*)d_in[7];
    const float* bl    = (const float*)d_in[8];
    float*       out   = (float*)d_out;

    const int TB = 256;
    k_init   <<<(N_NODES + TB - 1) / TB, TB>>>();
    k_hist   <<<(N_EDGES + TB - 1) / TB, TB>>>(ei);
    k_scan1  <<<NB, SCAN_B>>>();
    k_scan2  <<<1, 128>>>();
    k_scan3  <<<(N_NODES + TB - 1) / TB, TB>>>();
    k_l1_init<<<(N_NODES * F + TB - 1) / TB, TB>>>(x, W1);
    k_scatter<<<(N_EDGES + TB - 1) / TB, TB>>>(ei);
    k_agg1   <<<(N_NODES * 32 + TB - 1) / TB, TB>>>(b1, W2);
    k_agg2   <<<(N_NODES * 32 + TB - 1) / TB, TB>>>(b2, batch);
    k_out    <<<(N_GRAPHS * 2 + TB - 1) / TB, TB>>>(Wl, bl, out);
}